// round 15
// baseline (speedup 1.0000x reference)
#include <cuda_runtime.h>
#include <cuda_fp16.h>
#include <cstdint>

#define M_TOK   32768
#define N_CODE  8192
#define CDIM    256
#define DDIM    1024
#define TDIM    2048
#define BATCH   16

#define MARGIN   2.0f
#define DBIAS    16.0f
#define LO_SCALE 4096.0f
#define LO_INV   (1.0f / 4096.0f)

// ---------------- device scratch ----------------
__device__ float               g_woutT[CDIM * DDIM];
__device__ float               g_table[N_CODE * DDIM];
__device__ float               g_cnorm[N_CODE];
__device__ float               g_enc  [M_TOK * CDIM];        // fp32 enc (exact rerank)
__device__ __half              g_encH [M_TOK * CDIM];        // fp16 enc (coarse)
__device__ __half              g_cbH  [N_CODE * CDIM];       // fp16 codebook
__device__ __half              g_zh   [(size_t)M_TOK * DDIM];// z transposed, fp16 hi
__device__ __half              g_zl   [(size_t)M_TOK * DDIM];// (z-zh)*4096
__device__ __half              g_wh   [CDIM * DDIM];         // w_in (o,d) hi
__device__ __half              g_wl   [CDIM * DDIM];         // (w-wh)*4096
__device__ unsigned long long  g_part [(size_t)M_TOK * 512]; // 256 groups x top2
__device__ int                 g_idx  [M_TOK];

// ---------------- helpers ----------------
__device__ __forceinline__ uint32_t smem_u32(const void* p) {
    uint32_t a;
    asm("{ .reg .u64 t; cvta.to.shared.u64 t, %1; cvt.u32.u64 %0, t; }" : "=r"(a) : "l"(p));
    return a;
}
__device__ __forceinline__ unsigned long long u64min(unsigned long long a, unsigned long long b) {
    return a < b ? a : b;
}
__device__ __forceinline__ unsigned long long u64max(unsigned long long a, unsigned long long b) {
    return a > b ? a : b;
}

// f32x2 (Blackwell FFMA2) for the fp32 table GEMM
__device__ __forceinline__ unsigned long long pk2(float x, float y) {
    unsigned long long r;
    asm("mov.b64 %0, {%1, %2};" : "=l"(r) : "r"(__float_as_uint(x)), "r"(__float_as_uint(y)));
    return r;
}
__device__ __forceinline__ float2 upk2(unsigned long long v) {
    unsigned int lo, hi;
    asm("mov.b64 {%0, %1}, %2;" : "=r"(lo), "=r"(hi) : "l"(v));
    return make_float2(__uint_as_float(lo), __uint_as_float(hi));
}
#define FMA2(d, a, b) asm("fma.rn.f32x2 %0, %1, %2, %3;" : "=l"(d) : "l"(a), "l"(b), "l"(d))

// mma / ldmatrix / cp.async (plain PTX, sm_80+/75+)
#define LDSM_X4(r0, r1, r2, r3, addr) \
    asm volatile("ldmatrix.sync.aligned.m8n8.x4.shared.b16 {%0,%1,%2,%3}, [%4];" \
                 : "=r"(r0), "=r"(r1), "=r"(r2), "=r"(r3) : "r"(addr))
#define LDSM_X2(r0, r1, addr) \
    asm volatile("ldmatrix.sync.aligned.m8n8.x2.shared.b16 {%0,%1}, [%2];" \
                 : "=r"(r0), "=r"(r1) : "r"(addr))
#define MMA16816(c, a, b) \
    asm volatile("mma.sync.aligned.m16n8k16.row.col.f32.f16.f16.f32 " \
                 "{%0,%1,%2,%3},{%4,%5,%6,%7},{%8,%9},{%0,%1,%2,%3};" \
                 : "+f"((c)[0]), "+f"((c)[1]), "+f"((c)[2]), "+f"((c)[3]) \
                 : "r"((a)[0]), "r"((a)[1]), "r"((a)[2]), "r"((a)[3]), \
                   "r"((b)[0]), "r"((b)[1]))
#define MMA16816H(c, a, b) \
    asm volatile("mma.sync.aligned.m16n8k16.row.col.f16.f16.f16.f16 " \
                 "{%0,%1},{%2,%3,%4,%5},{%6,%7},{%0,%1};" \
                 : "+r"((c)[0]), "+r"((c)[1]) \
                 : "r"((a)[0]), "r"((a)[1]), "r"((a)[2]), "r"((a)[3]), \
                   "r"((b)[0]), "r"((b)[1]))
#define CP_ASYNC16(dst, src) \
    asm volatile("cp.async.cg.shared.global [%0], [%1], 16;" :: "r"(dst), "l"(src))
#define CP_COMMIT() asm volatile("cp.async.commit_group;")
#define CP_WAIT1()  asm volatile("cp.async.wait_group 1;")
#define CP_WAIT0()  asm volatile("cp.async.wait_group 0;")

// ---------------- fp32 FFMA2 micro-kernel (table GEMM) ----------------
__device__ __forceinline__ void mm_step(const float* __restrict__ As,
                                        const float* __restrict__ Bs,
                                        unsigned long long acc[8][4],
                                        int ty, int tx) {
#pragma unroll
    for (int k = 0; k < 16; k++) {
        const float4 a0 = *(const float4*)(As + k * 128 + ty * 8);
        const float4 a1 = *(const float4*)(As + k * 128 + ty * 8 + 4);
        const float4 b0 = *(const float4*)(Bs + k * 128 + tx * 8);
        const float4 b1 = *(const float4*)(Bs + k * 128 + tx * 8 + 4);
        unsigned long long bb0 = pk2(b0.x, b0.y);
        unsigned long long bb1 = pk2(b0.z, b0.w);
        unsigned long long bb2 = pk2(b1.x, b1.y);
        unsigned long long bb3 = pk2(b1.z, b1.w);
        float av[8] = {a0.x, a0.y, a0.z, a0.w, a1.x, a1.y, a1.z, a1.w};
#pragma unroll
        for (int i = 0; i < 8; i++) {
            unsigned long long aa = pk2(av[i], av[i]);
            FMA2(acc[i][0], aa, bb0);
            FMA2(acc[i][1], aa, bb1);
            FMA2(acc[i][2], aa, bb2);
            FMA2(acc[i][3], aa, bb3);
        }
    }
}

// ---------------- noop (shifts ncu capture window onto mega) ----------------
__global__ void noop_k() {}

// ---------------- prep mega-kernel ----------------
__global__ void prep_mega(const float* __restrict__ cb,
                          const float* __restrict__ in_v, const float* __restrict__ in_g,
                          const float* __restrict__ out_v, const float* __restrict__ out_g,
                          const float* __restrict__ z) {
    __shared__ float red[256];
    __shared__ float tile[64][65];
    int bi = blockIdx.x;
    int tid = threadIdx.x;

    if (bi < 8192) {
        int k = bi;
        float v = cb[k * CDIM + tid];
        red[tid] = v * v;
        __syncthreads();
        for (int st = 128; st; st >>= 1) {
            if (tid < st) red[tid] += red[tid + st];
            __syncthreads();
        }
        if (tid == 0) g_cnorm[k] = red[0];
        g_cbH[k * CDIM + tid] = __float2half_rn(v);
    } else if (bi < 8448) {
        int o = bi - 8192;
        float s = 0.f;
        for (int d = tid; d < DDIM; d += 256) {
            float v = in_v[o * DDIM + d];
            s += v * v;
        }
        red[tid] = s;
        __syncthreads();
        for (int st = 128; st; st >>= 1) {
            if (tid < st) red[tid] += red[tid + st];
            __syncthreads();
        }
        float scale = in_g[o] * rsqrtf(red[0]);
        for (int d = tid; d < DDIM; d += 256) {
            float w = in_v[o * DDIM + d] * scale;
            __half hi = __float2half_rn(w);
            __half lo = __float2half_rn((w - __half2float(hi)) * LO_SCALE);
            g_wh[o * DDIM + d] = hi;
            g_wl[o * DDIM + d] = lo;
        }
    } else if (bi < 9472) {
        int o = bi - 8448;
        float v = out_v[o * CDIM + tid];
        red[tid] = v * v;
        __syncthreads();
        for (int st = 128; st; st >>= 1) {
            if (tid < st) red[tid] += red[tid + st];
            __syncthreads();
        }
        float scale = out_g[o] * rsqrtf(red[0]);
        g_woutT[tid * DDIM + o] = v * scale;
    } else {
        int j = bi - 9472;
        int t0 = (j & 31) * 64, d0 = ((j >> 5) & 15) * 64, b = j >> 9;
#pragma unroll
        for (int p = 0; p < 16; p++) {
            int e = tid + p * 256;
            int i = e >> 6, jj = e & 63;
            tile[i][jj] = z[(size_t)b * DDIM * TDIM + (size_t)(d0 + i) * TDIM + t0 + jj];
        }
        __syncthreads();
#pragma unroll
        for (int p = 0; p < 16; p++) {
            int e = tid + p * 256;
            int i = e >> 6, jj = e & 63;
            float x = tile[jj][i];
            __half hi = __float2half_rn(x);
            __half lo = __float2half_rn((x - __half2float(hi)) * LO_SCALE);
            size_t off = (size_t)(b * TDIM + t0 + i) * DDIM + d0 + jj;
            g_zh[off] = hi;
            g_zl[off] = lo;
        }
    }
}

// ---------------- GEMM 1: enc via split-fp16 mma (R14 proven) ----------------
__global__ void __launch_bounds__(256, 2)
gemm_ze_mma(const float* __restrict__ in_b) {
    extern __shared__ __align__(128) char sm[];
    const int tid = threadIdx.x, lane = tid & 31, wid = tid >> 5;
    const int wm = wid >> 2, wn = wid & 3;
    const int bx = blockIdx.x, by = blockIdx.y;
    uint32_t smb = smem_u32(sm);

    float chh[2][4][4];
    float clo[2][4][4];
#pragma unroll
    for (int mt = 0; mt < 2; mt++)
#pragma unroll
        for (int nt = 0; nt < 4; nt++)
#pragma unroll
            for (int q = 0; q < 4; q++) { chh[mt][nt][q] = 0.f; clo[mt][nt][q] = 0.f; }

#define ZE_ISSUE(chunk, stage) do {                                              \
    uint32_t base_ = smb + (stage) * 24576u;                                     \
    size_t k0_ = (size_t)(chunk) * 32;                                           \
    {                                                                            \
        int r_ = tid >> 2, c_ = tid & 3;                                         \
        uint32_t sw_ = (uint32_t)(r_ * 64 + ((c_ ^ ((r_ >> 1) & 3)) * 16));      \
        size_t sa_ = (size_t)(by * 64 + r_) * DDIM + k0_ + c_ * 8;               \
        CP_ASYNC16(base_ + sw_,          (const char*)(g_zh + sa_));             \
        CP_ASYNC16(base_ + 4096u + sw_,  (const char*)(g_zl + sa_));             \
    }                                                                            \
    _Pragma("unroll")                                                            \
    for (int i_ = 0; i_ < 2; i_++) {                                             \
        int e_ = tid + i_ * 256;                                                 \
        int r_ = e_ >> 2, c_ = e_ & 3;                                           \
        uint32_t sw_ = (uint32_t)(r_ * 64 + ((c_ ^ ((r_ >> 1) & 3)) * 16));      \
        size_t sb_ = (size_t)(bx * 128 + r_) * DDIM + k0_ + c_ * 8;              \
        CP_ASYNC16(base_ + 8192u + sw_,   (const char*)(g_wh + sb_));            \
        CP_ASYNC16(base_ + 16384u + sw_,  (const char*)(g_wl + sb_));            \
    }                                                                            \
    CP_COMMIT();                                                                 \
} while (0)

    ZE_ISSUE(0, 0);
    ZE_ISSUE(1, 1);

    const int r7   = lane & 7;
    const int rA   = wm * 32 + (lane & 15);
    const int khA  = lane >> 4;
    const int nB4  = wn * 32 + ((lane >> 4) & 1) * 8 + r7;
    const int khB4 = (lane >> 3) & 1;
    const int rswA = (rA >> 1) & 3;
    const int rswB = (nB4 >> 1) & 3;

    uint32_t tA[2], tB[2];
#pragma unroll
    for (int kt = 0; kt < 2; kt++) {
        tA[kt] = (uint32_t)((((kt * 2 + khA)  ^ rswA)) * 16);
        tB[kt] = (uint32_t)((((kt * 2 + khB4) ^ rswB)) * 16);
    }
    uint32_t baseA_mt[2], baseB_n2[2];
#pragma unroll
    for (int mt = 0; mt < 2; mt++) baseA_mt[mt] = (uint32_t)((rA + mt * 16) * 64);
#pragma unroll
    for (int n2 = 0; n2 < 2; n2++) baseB_n2[n2] = (uint32_t)((nB4 + n2 * 16) * 64);

    for (int ch = 0; ch < 32; ch++) {
        int st = ch % 3;
        if (ch == 31) { CP_WAIT0(); } else { CP_WAIT1(); }
        __syncthreads();
        if (ch + 2 < 32) ZE_ISSUE(ch + 2, (ch + 2) % 3);

        uint32_t Ah = smb + st * 24576u;
        uint32_t Al = Ah + 4096u;
        uint32_t Bh = Ah + 8192u;
        uint32_t Bl = Ah + 16384u;
#pragma unroll
        for (int kt = 0; kt < 2; kt++) {
            uint32_t ah[2][4], al[2][4], bh[4][2], bl[4][2];
#pragma unroll
            for (int mt = 0; mt < 2; mt++) {
                LDSM_X4(ah[mt][0], ah[mt][1], ah[mt][2], ah[mt][3],
                        Ah + baseA_mt[mt] + tA[kt]);
                LDSM_X4(al[mt][0], al[mt][1], al[mt][2], al[mt][3],
                        Al + baseA_mt[mt] + tA[kt]);
            }
#pragma unroll
            for (int n2 = 0; n2 < 2; n2++) {
                LDSM_X4(bh[2 * n2][0], bh[2 * n2][1],
                        bh[2 * n2 + 1][0], bh[2 * n2 + 1][1],
                        Bh + baseB_n2[n2] + tB[kt]);
                LDSM_X4(bl[2 * n2][0], bl[2 * n2][1],
                        bl[2 * n2 + 1][0], bl[2 * n2 + 1][1],
                        Bl + baseB_n2[n2] + tB[kt]);
            }
#pragma unroll
            for (int mt = 0; mt < 2; mt++)
#pragma unroll
                for (int nt = 0; nt < 4; nt++) {
                    MMA16816(chh[mt][nt], ah[mt], bh[nt]);
                    MMA16816(clo[mt][nt], ah[mt], bl[nt]);
                    MMA16816(clo[mt][nt], al[mt], bh[nt]);
                }
        }
    }
#undef ZE_ISSUE

    float bias[4][2];
#pragma unroll
    for (int nt = 0; nt < 4; nt++) {
        int col0 = bx * 128 + wn * 32 + nt * 8 + (lane & 3) * 2;
        bias[nt][0] = in_b[col0];
        bias[nt][1] = in_b[col0 + 1];
    }
#pragma unroll
    for (int mt = 0; mt < 2; mt++) {
#pragma unroll
        for (int h = 0; h < 2; h++) {
            int row = by * 64 + wm * 32 + mt * 16 + (lane >> 2) + h * 8;
#pragma unroll
            for (int nt = 0; nt < 4; nt++) {
                int col0 = bx * 128 + wn * 32 + nt * 8 + (lane & 3) * 2;
                float v0 = chh[mt][nt][h * 2 + 0] + clo[mt][nt][h * 2 + 0] * LO_INV + bias[nt][0];
                float v1 = chh[mt][nt][h * 2 + 1] + clo[mt][nt][h * 2 + 1] * LO_INV + bias[nt][1];
                *(float2*)(g_enc + (size_t)row * CDIM + col0) = make_float2(v0, v1);
                __half2 hp = __floats2half2_rn(v0, v1);
                *(__half2*)(g_encH + (size_t)row * CDIM + col0) = hp;
            }
        }
    }
}

// ---------------- mega kernel: [0,512) table GEMM | [512,8704) coarse -------
// coarse: CTA 128 tokens x 256 codes, 8 warps 2x4 (warp tile 64x64),
// fp16 accumulators (64 regs), 2-stage x 48KB -> 2 CTAs/SM (16 warps)
__global__ void __launch_bounds__(256, 2)
mega_coarse_table(const float* __restrict__ cbk) {
    extern __shared__ __align__(128) char sm[];
    const int tid = threadIdx.x, lane = tid & 31, wid = tid >> 5;
    uint32_t smb = smem_u32(sm);

    if (blockIdx.x < 512) {
        int bx = blockIdx.x & 7;
        int by = blockIdx.x >> 3;
        int tx = tid & 15, ty = tid >> 4;
        float* As = (float*)sm;
        float* Bs = As + 2048;

        unsigned long long acc[8][4];
#pragma unroll
        for (int i = 0; i < 8; i++)
#pragma unroll
            for (int j = 0; j < 4; j++) acc[i][j] = 0ull;

        const float* Ab = cbk + (size_t)(by * 128) * CDIM;
        const float* Bb = g_woutT + bx * 128;

        for (int k0 = 0; k0 < CDIM; k0 += 16) {
#pragma unroll
            for (int it = 0; it < 2; it++) {
                int e  = tid + it * 256;
                int r  = e >> 2;
                int kf = (e & 3) * 4;
                float4 va = *(const float4*)(Ab + (size_t)r * CDIM + k0 + kf);
                As[(kf + 0) * 128 + r] = va.x;
                As[(kf + 1) * 128 + r] = va.y;
                As[(kf + 2) * 128 + r] = va.z;
                As[(kf + 3) * 128 + r] = va.w;
                int k  = e >> 5;
                int n4 = (e & 31) * 4;
                *(float4*)&Bs[k * 128 + n4] = *(const float4*)(Bb + (size_t)(k0 + k) * DDIM + n4);
            }
            __syncthreads();
            mm_step(As, Bs, acc, ty, tx);
            __syncthreads();
        }

        int nbase = bx * 128 + tx * 8;
#pragma unroll
        for (int i = 0; i < 8; i++) {
            int row = by * 128 + ty * 8 + i;
            float* dst = g_table + (size_t)row * DDIM + nbase;
            float2 v0 = upk2(acc[i][0]), v1 = upk2(acc[i][1]);
            float2 v2 = upk2(acc[i][2]), v3 = upk2(acc[i][3]);
            *(float4*)dst       = make_float4(v0.x, v0.y, v1.x, v1.y);
            *(float4*)(dst + 4) = make_float4(v2.x, v2.y, v3.x, v3.y);
        }
        return;
    }

    // ---- coarse path: 128x256 tile, fp16 accumulators ----
    int cidx = blockIdx.x - 512;
    const int bx = cidx & 31;   // code tile (0..31), 256 codes each
    const int by = cidx >> 5;   // token tile (0..255)
    const int wm = wid >> 2, wn = wid & 3;   // 2 x 4 warps -> warp tile 64x64

    uint32_t c[4][8][2];   // fp16x2 accumulators
#pragma unroll
    for (int mt = 0; mt < 4; mt++)
#pragma unroll
        for (int nt = 0; nt < 8; nt++) { c[mt][nt][0] = 0u; c[mt][nt][1] = 0u; }

    const char* baseA = (const char*)g_encH + (size_t)(by * 128) * 512;
    const char* baseB = (const char*)g_cbH  + (size_t)(bx * 256) * 512;

#define ISSUE_CHUNK(chunk, stage) do {                                           \
    uint32_t dA = smb + (stage) * 49152u;                                        \
    uint32_t dB = dA + 16384u;                                                   \
    _Pragma("unroll")                                                            \
    for (int i_ = 0; i_ < 4; i_++) {                                             \
        int e_ = tid + i_ * 256;                                                 \
        int row_ = e_ >> 3, cc_ = e_ & 7;                                        \
        uint32_t sw_ = (uint32_t)((cc_ ^ (row_ & 7)) * 16);                      \
        CP_ASYNC16(dA + row_ * 128 + sw_,                                        \
                   baseA + (size_t)row_ * 512 + (chunk) * 128 + cc_ * 16);       \
    }                                                                            \
    _Pragma("unroll")                                                            \
    for (int i_ = 0; i_ < 8; i_++) {                                             \
        int e_ = tid + i_ * 256;                                                 \
        int row_ = e_ >> 3, cc_ = e_ & 7;                                        \
        uint32_t sw_ = (uint32_t)((cc_ ^ (row_ & 7)) * 16);                      \
        CP_ASYNC16(dB + row_ * 128 + sw_,                                        \
                   baseB + (size_t)row_ * 512 + (chunk) * 128 + cc_ * 16);       \
    }                                                                            \
    CP_COMMIT();                                                                 \
} while (0)

    ISSUE_CHUNK(0, 0);
    ISSUE_CHUNK(1, 1);

    const int r7   = lane & 7;
    const int rA   = wm * 64 + (lane & 15);
    const int khA  = lane >> 4;
    const int nB4  = wn * 64 + ((lane >> 4) & 1) * 8 + r7;
    const int khB4 = (lane >> 3) & 1;

    uint32_t tA[4], tB[4];
#pragma unroll
    for (int kt = 0; kt < 4; kt++) {
        tA[kt] = (uint32_t)((((kt * 2 + khA)  ^ r7)) * 16);
        tB[kt] = (uint32_t)((((kt * 2 + khB4) ^ r7)) * 16);
    }
    uint32_t baseA_mt[4], baseB_n2[4];
#pragma unroll
    for (int mt = 0; mt < 4; mt++) baseA_mt[mt] = (uint32_t)((rA + mt * 16) * 128);
#pragma unroll
    for (int n2 = 0; n2 < 4; n2++) baseB_n2[n2] = (uint32_t)((nB4 + n2 * 16) * 128);

    for (int ch = 0; ch < 4; ch++) {
        int st = ch & 1;
        if (ch == 3) { CP_WAIT0(); } else { CP_WAIT1(); }
        __syncthreads();

        uint32_t Ab = smb + st * 49152u;
        uint32_t Bb = Ab + 16384u;
#pragma unroll
        for (int kt = 0; kt < 4; kt++) {
            uint32_t a[4][4], bfr[8][2];
#pragma unroll
            for (int mt = 0; mt < 4; mt++) {
                LDSM_X4(a[mt][0], a[mt][1], a[mt][2], a[mt][3],
                        Ab + baseA_mt[mt] + tA[kt]);
            }
#pragma unroll
            for (int n2 = 0; n2 < 4; n2++) {
                LDSM_X4(bfr[2 * n2][0], bfr[2 * n2][1],
                        bfr[2 * n2 + 1][0], bfr[2 * n2 + 1][1],
                        Bb + baseB_n2[n2] + tB[kt]);
            }
#pragma unroll
            for (int mt = 0; mt < 4; mt++)
#pragma unroll
                for (int nt = 0; nt < 8; nt++) MMA16816H(c[mt][nt], a[mt], bfr[nt]);
        }

        if (ch + 2 < 4) {
            __syncthreads();
            ISSUE_CHUNK(ch + 2, st);
        }
    }
#undef ISSUE_CHUNK

    // epilogue: convert fp16 pairs, biased packing, 2 groups of 32 per warp
    float cn16[8][2];
#pragma unroll
    for (int nt = 0; nt < 8; nt++) {
        int col0 = bx * 256 + wn * 64 + nt * 8 + (lane & 3) * 2;
        cn16[nt][0] = g_cnorm[col0]     + DBIAS;
        cn16[nt][1] = g_cnorm[col0 + 1] + DBIAS;
    }
#pragma unroll
    for (int mt = 0; mt < 4; mt++) {
#pragma unroll
        for (int h = 0; h < 2; h++) {
#pragma unroll
            for (int grp = 0; grp < 2; grp++) {
                unsigned long long b1 = ~0ull, b2 = ~0ull;
#pragma unroll
                for (int n = 0; n < 4; n++) {
                    int nt = grp * 4 + n;
                    float2 v = __half22float2(*(__half2*)&c[mt][nt][h]);
#pragma unroll
                    for (int j = 0; j < 2; j++) {
                        int col = bx * 256 + wn * 64 + nt * 8 + (lane & 3) * 2 + j;
                        float pv = (j == 0) ? v.x : v.y;
                        float d = fmaf(-2.f, pv, cn16[nt][j]);
                        unsigned long long p =
                            ((unsigned long long)__float_as_uint(d) << 32) | (unsigned)col;
                        if (p < b1) { b2 = b1; b1 = p; }
                        else if (p < b2) { b2 = p; }
                    }
                }
#pragma unroll
                for (int x = 1; x <= 2; x <<= 1) {
                    unsigned long long o1 = __shfl_xor_sync(0xFFFFFFFFu, b1, x);
                    unsigned long long o2 = __shfl_xor_sync(0xFFFFFFFFu, b2, x);
                    unsigned long long w1 = u64min(b1, o1);
                    unsigned long long l1 = u64max(b1, o1);
                    b2 = u64min(l1, u64min(b2, o2));
                    b1 = w1;
                }
                if ((lane & 3) == 0) {
                    int token = by * 128 + wm * 64 + mt * 16 + (lane >> 2) + h * 8;
                    int g = bx * 8 + wn * 2 + grp;
                    g_part[(size_t)token * 512 + g * 2 + 0] = b1;
                    g_part[(size_t)token * 512 + g * 2 + 1] = b2;
                }
            }
        }
    }
}

// ---------------- select: coarse min + margin + exact fp32 rerank ----------------
__global__ void __launch_bounds__(256)
select_k(const float* __restrict__ cbk, float* __restrict__ out_idx) {
    __shared__ int s_cnt[8];
    __shared__ unsigned s_code[8][64];
    int w = threadIdx.x >> 5, lane = threadIdx.x & 31;
    int token = blockIdx.x * 8 + w;
    if (lane == 0) s_cnt[w] = 0;
    __syncwarp();

    unsigned long long v[16];
    unsigned long long m = ~0ull;
#pragma unroll
    for (int i = 0; i < 16; i++) {
        v[i] = g_part[(size_t)token * 512 + i * 32 + lane];
        m = u64min(m, v[i]);
    }
#pragma unroll
    for (int x = 16; x; x >>= 1) {
        unsigned long long o = __shfl_xor_sync(0xFFFFFFFFu, m, x);
        m = u64min(m, o);
    }
    unsigned ub = (unsigned)(m >> 32);
    float dbest_b = __uint_as_float(ub);
    unsigned tb = __float_as_uint(dbest_b + MARGIN);
#pragma unroll
    for (int i = 0; i < 16; i++) {
        if ((unsigned)(v[i] >> 32) <= tb) {
            int p = atomicAdd(&s_cnt[w], 1);
            if (p < 64) s_code[w][p] = (unsigned)v[i];
        }
    }
    __syncwarp();
    int n = s_cnt[w] < 64 ? s_cnt[w] : 64;

    unsigned winner;
    if (n <= 1) {
        winner = (unsigned)m;
    } else {
        float e[8];
        *(float4*)e       = *(const float4*)(g_enc + (size_t)token * 256 + lane * 8);
        *(float4*)(e + 4) = *(const float4*)(g_enc + (size_t)token * 256 + lane * 8 + 4);
        unsigned long long best = ~0ull;
        for (int s = 0; s < n; s++) {
            unsigned code = s_code[w][s];
            const float* cr = cbk + (size_t)code * 256 + lane * 8;
            float part = 0.f;
#pragma unroll
            for (int j = 0; j < 8; j++) part += e[j] * cr[j];
#pragma unroll
            for (int x = 16; x; x >>= 1) part += __shfl_xor_sync(0xFFFFFFFFu, part, x);
            float d = g_cnorm[code] - 2.f * part + DBIAS;
            unsigned long long p = ((unsigned long long)__float_as_uint(d) << 32) | code;
            best = u64min(best, p);
        }
        winner = (unsigned)best;
    }
    if (lane == 0) {
        g_idx[token] = (int)winner;
        if (out_idx) out_idx[token] = (float)winner;
    }
}

// ---------------- gather (o-dim split across gridDim.z = 4) ----------------
__global__ void gather_out(const float* __restrict__ out_b, float* __restrict__ out) {
    int b  = blockIdx.y;
    int t0 = blockIdx.x * 64;
    int obase = blockIdx.z * (DDIM / 4);
    __shared__ float sm[64][65];
    __shared__ int sidx[64];
    int tid = threadIdx.x;
    if (tid < 64) sidx[tid] = g_idx[b * TDIM + t0 + tid];
    __syncthreads();

    for (int o0 = obase; o0 < obase + DDIM / 4; o0 += 64) {
#pragma unroll
        for (int p = 0; p < 16; p++) {
            int e  = tid + p * 256;
            int tl = e >> 6, ol = e & 63;
            sm[tl][ol] = g_table[(size_t)sidx[tl] * DDIM + o0 + ol];
        }
        __syncthreads();
#pragma unroll
        for (int p = 0; p < 16; p++) {
            int e  = tid + p * 256;
            int ol = e >> 6, tl = e & 63;
            out[(size_t)b * DDIM * TDIM + (size_t)(o0 + ol) * TDIM + t0 + tl] =
                sm[tl][ol] + out_b[o0 + ol];
        }
        __syncthreads();
    }
}

// ---------------- launch ----------------
extern "C" void kernel_launch(void* const* d_in, const int* in_sizes, int n_in,
                              void* d_out, int out_size) {
    const float* z     = (const float*)d_in[0];
    const float* in_v  = (const float*)d_in[1];
    const float* in_g  = (const float*)d_in[2];
    const float* in_b  = (const float*)d_in[3];
    const float* out_v = (const float*)d_in[4];
    const float* out_g = (const float*)d_in[5];
    const float* out_b = (const float*)d_in[6];
    const float* cbk   = (const float*)d_in[7];
    float* out = (float*)d_out;

    cudaFuncSetAttribute(gemm_ze_mma, cudaFuncAttributeMaxDynamicSharedMemorySize, 73728);
    cudaFuncSetAttribute(mega_coarse_table, cudaFuncAttributeMaxDynamicSharedMemorySize, 98304);

    const long long out_elems = (long long)BATCH * DDIM * TDIM;
    float* idx_dst = (out_size >= out_elems + M_TOK) ? out + out_elems : nullptr;

    noop_k           <<<1, 32>>>();                                        // 1
    prep_mega        <<<17664, 256>>>(cbk, in_v, in_g, out_v, out_g, z);   // 2
    gemm_ze_mma      <<<dim3(2, 512), 256, 73728>>>(in_b);                 // 3
    mega_coarse_table<<<8704, 256, 98304>>>(cbk);                          // 4  <- profiled
    select_k         <<<M_TOK / 8, 256>>>(cbk, idx_dst);                   // 5
    gather_out       <<<dim3(TDIM / 64, BATCH, 4), 256>>>(out_b, out);     // 6
}

// round 16
// speedup vs baseline: 1.0594x; 1.0594x over previous
#include <cuda_runtime.h>
#include <cuda_fp16.h>
#include <cstdint>

#define M_TOK   32768
#define N_CODE  8192
#define CDIM    256
#define DDIM    1024
#define TDIM    2048
#define BATCH   16

#define MARGIN   0.25f
#define DBIAS    16.0f
#define LO_SCALE 4096.0f
#define LO_INV   (1.0f / 4096.0f)

// ---------------- device scratch ----------------
__device__ float               g_woutT[CDIM * DDIM];
__device__ float               g_table[N_CODE * DDIM];
__device__ float               g_cnorm[N_CODE];
__device__ float               g_enc  [M_TOK * CDIM];        // fp32 enc (exact rerank)
__device__ __half              g_encH [M_TOK * CDIM];        // fp16 enc (coarse)
__device__ __half              g_cbH  [N_CODE * CDIM];       // fp16 codebook
__device__ __half              g_zh   [(size_t)M_TOK * DDIM];// z transposed, fp16 hi
__device__ __half              g_zl   [(size_t)M_TOK * DDIM];// (z-zh)*4096
__device__ __half              g_wh   [CDIM * DDIM];         // w_in (o,d) hi
__device__ __half              g_wl   [CDIM * DDIM];         // (w-wh)*4096
__device__ unsigned long long  g_part [(size_t)M_TOK * 512]; // 256 groups x top2
__device__ int                 g_idx  [M_TOK];

// ---------------- helpers ----------------
__device__ __forceinline__ uint32_t smem_u32(const void* p) {
    uint32_t a;
    asm("{ .reg .u64 t; cvta.to.shared.u64 t, %1; cvt.u32.u64 %0, t; }" : "=r"(a) : "l"(p));
    return a;
}
__device__ __forceinline__ unsigned long long u64min(unsigned long long a, unsigned long long b) {
    return a < b ? a : b;
}
__device__ __forceinline__ unsigned long long u64max(unsigned long long a, unsigned long long b) {
    return a > b ? a : b;
}

// f32x2 (Blackwell FFMA2) for the fp32 table GEMM
__device__ __forceinline__ unsigned long long pk2(float x, float y) {
    unsigned long long r;
    asm("mov.b64 %0, {%1, %2};" : "=l"(r) : "r"(__float_as_uint(x)), "r"(__float_as_uint(y)));
    return r;
}
__device__ __forceinline__ float2 upk2(unsigned long long v) {
    unsigned int lo, hi;
    asm("mov.b64 {%0, %1}, %2;" : "=r"(lo), "=r"(hi) : "l"(v));
    return make_float2(__uint_as_float(lo), __uint_as_float(hi));
}
#define FMA2(d, a, b) asm("fma.rn.f32x2 %0, %1, %2, %3;" : "=l"(d) : "l"(a), "l"(b), "l"(d))

// mma / ldmatrix / cp.async (plain PTX, sm_80+/75+)
#define LDSM_X4(r0, r1, r2, r3, addr) \
    asm volatile("ldmatrix.sync.aligned.m8n8.x4.shared.b16 {%0,%1,%2,%3}, [%4];" \
                 : "=r"(r0), "=r"(r1), "=r"(r2), "=r"(r3) : "r"(addr))
#define LDSM_X2(r0, r1, addr) \
    asm volatile("ldmatrix.sync.aligned.m8n8.x2.shared.b16 {%0,%1}, [%2];" \
                 : "=r"(r0), "=r"(r1) : "r"(addr))
#define MMA16816(c, a, b) \
    asm volatile("mma.sync.aligned.m16n8k16.row.col.f32.f16.f16.f32 " \
                 "{%0,%1,%2,%3},{%4,%5,%6,%7},{%8,%9},{%0,%1,%2,%3};" \
                 : "+f"((c)[0]), "+f"((c)[1]), "+f"((c)[2]), "+f"((c)[3]) \
                 : "r"((a)[0]), "r"((a)[1]), "r"((a)[2]), "r"((a)[3]), \
                   "r"((b)[0]), "r"((b)[1]))
#define CP_ASYNC16(dst, src) \
    asm volatile("cp.async.cg.shared.global [%0], [%1], 16;" :: "r"(dst), "l"(src))
#define CP_COMMIT() asm volatile("cp.async.commit_group;")
#define CP_WAIT1()  asm volatile("cp.async.wait_group 1;")
#define CP_WAIT0()  asm volatile("cp.async.wait_group 0;")

// ---------------- fp32 FFMA2 micro-kernel (table GEMM) ----------------
__device__ __forceinline__ void mm_step(const float* __restrict__ As,
                                        const float* __restrict__ Bs,
                                        unsigned long long acc[8][4],
                                        int ty, int tx) {
#pragma unroll
    for (int k = 0; k < 16; k++) {
        const float4 a0 = *(const float4*)(As + k * 128 + ty * 8);
        const float4 a1 = *(const float4*)(As + k * 128 + ty * 8 + 4);
        const float4 b0 = *(const float4*)(Bs + k * 128 + tx * 8);
        const float4 b1 = *(const float4*)(Bs + k * 128 + tx * 8 + 4);
        unsigned long long bb0 = pk2(b0.x, b0.y);
        unsigned long long bb1 = pk2(b0.z, b0.w);
        unsigned long long bb2 = pk2(b1.x, b1.y);
        unsigned long long bb3 = pk2(b1.z, b1.w);
        float av[8] = {a0.x, a0.y, a0.z, a0.w, a1.x, a1.y, a1.z, a1.w};
#pragma unroll
        for (int i = 0; i < 8; i++) {
            unsigned long long aa = pk2(av[i], av[i]);
            FMA2(acc[i][0], aa, bb0);
            FMA2(acc[i][1], aa, bb1);
            FMA2(acc[i][2], aa, bb2);
            FMA2(acc[i][3], aa, bb3);
        }
    }
}

// ---------------- prep mega-kernel ----------------
// segments: [0,1024) cbH+cnorm (warp-per-row) | [1024,1280) win |
//           [1280,2304) wout | [2304,10496) conv_z
__global__ void prep_mega(const float* __restrict__ cb,
                          const float* __restrict__ in_v, const float* __restrict__ in_g,
                          const float* __restrict__ out_v, const float* __restrict__ out_g,
                          const float* __restrict__ z) {
    __shared__ float red[256];
    __shared__ float tile[64][65];
    int bi = blockIdx.x;
    int tid = threadIdx.x;

    if (bi < 1024) {
        // cbH + cnorm: warp per codebook row, no CTA syncs
        int k = bi * 8 + (tid >> 5);
        int lane = tid & 31;
        const float* row = cb + (size_t)k * CDIM + lane * 8;
        float4 va = *(const float4*)row;
        float4 vb = *(const float4*)(row + 4);
        float s = va.x * va.x + va.y * va.y + va.z * va.z + va.w * va.w
                + vb.x * vb.x + vb.y * vb.y + vb.z * vb.z + vb.w * vb.w;
#pragma unroll
        for (int x = 16; x; x >>= 1) s += __shfl_xor_sync(0xFFFFFFFFu, s, x);
        if (lane == 0) g_cnorm[k] = s;
        __half h[8];
        h[0] = __float2half_rn(va.x); h[1] = __float2half_rn(va.y);
        h[2] = __float2half_rn(va.z); h[3] = __float2half_rn(va.w);
        h[4] = __float2half_rn(vb.x); h[5] = __float2half_rn(vb.y);
        h[6] = __float2half_rn(vb.z); h[7] = __float2half_rn(vb.w);
        *(uint4*)(g_cbH + (size_t)k * CDIM + lane * 8) = *(uint4*)h;
    } else if (bi < 1280) {
        int o = bi - 1024;
        float s = 0.f;
        for (int d = tid; d < DDIM; d += 256) {
            float v = in_v[o * DDIM + d];
            s += v * v;
        }
        red[tid] = s;
        __syncthreads();
        for (int st = 128; st; st >>= 1) {
            if (tid < st) red[tid] += red[tid + st];
            __syncthreads();
        }
        float scale = in_g[o] * rsqrtf(red[0]);
        for (int d = tid; d < DDIM; d += 256) {
            float w = in_v[o * DDIM + d] * scale;
            __half hi = __float2half_rn(w);
            __half lo = __float2half_rn((w - __half2float(hi)) * LO_SCALE);
            g_wh[o * DDIM + d] = hi;
            g_wl[o * DDIM + d] = lo;
        }
    } else if (bi < 2304) {
        int o = bi - 1280;
        float v = out_v[o * CDIM + tid];
        red[tid] = v * v;
        __syncthreads();
        for (int st = 128; st; st >>= 1) {
            if (tid < st) red[tid] += red[tid + st];
            __syncthreads();
        }
        float scale = out_g[o] * rsqrtf(red[0]);
        g_woutT[tid * DDIM + o] = v * scale;
    } else {
        int j = bi - 2304;
        int t0 = (j & 31) * 64, d0 = ((j >> 5) & 15) * 64, b = j >> 9;
#pragma unroll
        for (int p = 0; p < 16; p++) {
            int e = tid + p * 256;
            int i = e >> 6, jj = e & 63;
            tile[i][jj] = z[(size_t)b * DDIM * TDIM + (size_t)(d0 + i) * TDIM + t0 + jj];
        }
        __syncthreads();
#pragma unroll
        for (int p = 0; p < 16; p++) {
            int e = tid + p * 256;
            int i = e >> 6, jj = e & 63;
            float x = tile[jj][i];
            __half hi = __float2half_rn(x);
            __half lo = __float2half_rn((x - __half2float(hi)) * LO_SCALE);
            size_t off = (size_t)(b * TDIM + t0 + i) * DDIM + d0 + jj;
            g_zh[off] = hi;
            g_zl[off] = lo;
        }
    }
}

// ---------------- GEMM 1: enc via split-fp16 mma (R14 proven) ----------------
__global__ void __launch_bounds__(256, 2)
gemm_ze_mma(const float* __restrict__ in_b) {
    extern __shared__ __align__(128) char sm[];
    const int tid = threadIdx.x, lane = tid & 31, wid = tid >> 5;
    const int wm = wid >> 2, wn = wid & 3;
    const int bx = blockIdx.x, by = blockIdx.y;
    uint32_t smb = smem_u32(sm);

    float chh[2][4][4];
    float clo[2][4][4];
#pragma unroll
    for (int mt = 0; mt < 2; mt++)
#pragma unroll
        for (int nt = 0; nt < 4; nt++)
#pragma unroll
            for (int q = 0; q < 4; q++) { chh[mt][nt][q] = 0.f; clo[mt][nt][q] = 0.f; }

#define ZE_ISSUE(chunk, stage) do {                                              \
    uint32_t base_ = smb + (stage) * 24576u;                                     \
    size_t k0_ = (size_t)(chunk) * 32;                                           \
    {                                                                            \
        int r_ = tid >> 2, c_ = tid & 3;                                         \
        uint32_t sw_ = (uint32_t)(r_ * 64 + ((c_ ^ ((r_ >> 1) & 3)) * 16));      \
        size_t sa_ = (size_t)(by * 64 + r_) * DDIM + k0_ + c_ * 8;               \
        CP_ASYNC16(base_ + sw_,          (const char*)(g_zh + sa_));             \
        CP_ASYNC16(base_ + 4096u + sw_,  (const char*)(g_zl + sa_));             \
    }                                                                            \
    _Pragma("unroll")                                                            \
    for (int i_ = 0; i_ < 2; i_++) {                                             \
        int e_ = tid + i_ * 256;                                                 \
        int r_ = e_ >> 2, c_ = e_ & 3;                                           \
        uint32_t sw_ = (uint32_t)(r_ * 64 + ((c_ ^ ((r_ >> 1) & 3)) * 16));      \
        size_t sb_ = (size_t)(bx * 128 + r_) * DDIM + k0_ + c_ * 8;              \
        CP_ASYNC16(base_ + 8192u + sw_,   (const char*)(g_wh + sb_));            \
        CP_ASYNC16(base_ + 16384u + sw_,  (const char*)(g_wl + sb_));            \
    }                                                                            \
    CP_COMMIT();                                                                 \
} while (0)

    ZE_ISSUE(0, 0);
    ZE_ISSUE(1, 1);

    const int r7   = lane & 7;
    const int rA   = wm * 32 + (lane & 15);
    const int khA  = lane >> 4;
    const int nB4  = wn * 32 + ((lane >> 4) & 1) * 8 + r7;
    const int khB4 = (lane >> 3) & 1;
    const int rswA = (rA >> 1) & 3;
    const int rswB = (nB4 >> 1) & 3;

    uint32_t tA[2], tB[2];
#pragma unroll
    for (int kt = 0; kt < 2; kt++) {
        tA[kt] = (uint32_t)((((kt * 2 + khA)  ^ rswA)) * 16);
        tB[kt] = (uint32_t)((((kt * 2 + khB4) ^ rswB)) * 16);
    }
    uint32_t baseA_mt[2], baseB_n2[2];
#pragma unroll
    for (int mt = 0; mt < 2; mt++) baseA_mt[mt] = (uint32_t)((rA + mt * 16) * 64);
#pragma unroll
    for (int n2 = 0; n2 < 2; n2++) baseB_n2[n2] = (uint32_t)((nB4 + n2 * 16) * 64);

    for (int ch = 0; ch < 32; ch++) {
        int st = ch % 3;
        if (ch == 31) { CP_WAIT0(); } else { CP_WAIT1(); }
        __syncthreads();
        if (ch + 2 < 32) ZE_ISSUE(ch + 2, (ch + 2) % 3);

        uint32_t Ah = smb + st * 24576u;
        uint32_t Al = Ah + 4096u;
        uint32_t Bh = Ah + 8192u;
        uint32_t Bl = Ah + 16384u;
#pragma unroll
        for (int kt = 0; kt < 2; kt++) {
            uint32_t ah[2][4], al[2][4], bh[4][2], bl[4][2];
#pragma unroll
            for (int mt = 0; mt < 2; mt++) {
                LDSM_X4(ah[mt][0], ah[mt][1], ah[mt][2], ah[mt][3],
                        Ah + baseA_mt[mt] + tA[kt]);
                LDSM_X4(al[mt][0], al[mt][1], al[mt][2], al[mt][3],
                        Al + baseA_mt[mt] + tA[kt]);
            }
#pragma unroll
            for (int n2 = 0; n2 < 2; n2++) {
                LDSM_X4(bh[2 * n2][0], bh[2 * n2][1],
                        bh[2 * n2 + 1][0], bh[2 * n2 + 1][1],
                        Bh + baseB_n2[n2] + tB[kt]);
                LDSM_X4(bl[2 * n2][0], bl[2 * n2][1],
                        bl[2 * n2 + 1][0], bl[2 * n2 + 1][1],
                        Bl + baseB_n2[n2] + tB[kt]);
            }
#pragma unroll
            for (int mt = 0; mt < 2; mt++)
#pragma unroll
                for (int nt = 0; nt < 4; nt++) {
                    MMA16816(chh[mt][nt], ah[mt], bh[nt]);
                    MMA16816(clo[mt][nt], ah[mt], bl[nt]);
                    MMA16816(clo[mt][nt], al[mt], bh[nt]);
                }
        }
    }
#undef ZE_ISSUE

    float bias[4][2];
#pragma unroll
    for (int nt = 0; nt < 4; nt++) {
        int col0 = bx * 128 + wn * 32 + nt * 8 + (lane & 3) * 2;
        bias[nt][0] = in_b[col0];
        bias[nt][1] = in_b[col0 + 1];
    }
#pragma unroll
    for (int mt = 0; mt < 2; mt++) {
#pragma unroll
        for (int h = 0; h < 2; h++) {
            int row = by * 64 + wm * 32 + mt * 16 + (lane >> 2) + h * 8;
#pragma unroll
            for (int nt = 0; nt < 4; nt++) {
                int col0 = bx * 128 + wn * 32 + nt * 8 + (lane & 3) * 2;
                float v0 = chh[mt][nt][h * 2 + 0] + clo[mt][nt][h * 2 + 0] * LO_INV + bias[nt][0];
                float v1 = chh[mt][nt][h * 2 + 1] + clo[mt][nt][h * 2 + 1] * LO_INV + bias[nt][1];
                *(float2*)(g_enc + (size_t)row * CDIM + col0) = make_float2(v0, v1);
                __half2 hp = __floats2half2_rn(v0, v1);
                *(__half2*)(g_encH + (size_t)row * CDIM + col0) = hp;
            }
        }
    }
}

// ---------------- mega kernel: [0,512) table GEMM | [512,16896) coarse ------
// (exact R10/R14 configuration: 256 threads, warp tile 64x32, 3-stage x 32KB)
__global__ void __launch_bounds__(256, 2)
mega_coarse_table(const float* __restrict__ cbk) {
    extern __shared__ __align__(128) char sm[];
    const int tid = threadIdx.x, lane = tid & 31, wid = tid >> 5;
    uint32_t smb = smem_u32(sm);

    if (blockIdx.x < 512) {
        int bx = blockIdx.x & 7;
        int by = blockIdx.x >> 3;
        int tx = tid & 15, ty = tid >> 4;
        float* As = (float*)sm;
        float* Bs = As + 2048;

        unsigned long long acc[8][4];
#pragma unroll
        for (int i = 0; i < 8; i++)
#pragma unroll
            for (int j = 0; j < 4; j++) acc[i][j] = 0ull;

        const float* Ab = cbk + (size_t)(by * 128) * CDIM;
        const float* Bb = g_woutT + bx * 128;

        for (int k0 = 0; k0 < CDIM; k0 += 16) {
#pragma unroll
            for (int it = 0; it < 2; it++) {
                int e  = tid + it * 256;
                int r  = e >> 2;
                int kf = (e & 3) * 4;
                float4 va = *(const float4*)(Ab + (size_t)r * CDIM + k0 + kf);
                As[(kf + 0) * 128 + r] = va.x;
                As[(kf + 1) * 128 + r] = va.y;
                As[(kf + 2) * 128 + r] = va.z;
                As[(kf + 3) * 128 + r] = va.w;
                int k  = e >> 5;
                int n4 = (e & 31) * 4;
                *(float4*)&Bs[k * 128 + n4] = *(const float4*)(Bb + (size_t)(k0 + k) * DDIM + n4);
            }
            __syncthreads();
            mm_step(As, Bs, acc, ty, tx);
            __syncthreads();
        }

        int nbase = bx * 128 + tx * 8;
#pragma unroll
        for (int i = 0; i < 8; i++) {
            int row = by * 128 + ty * 8 + i;
            float* dst = g_table + (size_t)row * DDIM + nbase;
            float2 v0 = upk2(acc[i][0]), v1 = upk2(acc[i][1]);
            float2 v2 = upk2(acc[i][2]), v3 = upk2(acc[i][3]);
            *(float4*)dst       = make_float4(v0.x, v0.y, v1.x, v1.y);
            *(float4*)(dst + 4) = make_float4(v2.x, v2.y, v3.x, v3.y);
        }
        return;
    }

    // ---- coarse path (R10) ----
    int cidx = blockIdx.x - 512;
    const int bx = cidx & 63;
    const int by = cidx >> 6;
    const int wm = wid >> 2, wn = wid & 3;

    float c[4][4][4];
#pragma unroll
    for (int mt = 0; mt < 4; mt++)
#pragma unroll
        for (int nt = 0; nt < 4; nt++)
#pragma unroll
            for (int q = 0; q < 4; q++) c[mt][nt][q] = 0.f;

    const char* baseA = (const char*)g_encH + (size_t)(by * 128) * 512;
    const char* baseB = (const char*)g_cbH  + (size_t)(bx * 128) * 512;

#define ISSUE_CHUNK(chunk, stage) do {                                           \
    uint32_t dA = smb + (stage) * 32768u;                                        \
    uint32_t dB = dA + 16384u;                                                   \
    _Pragma("unroll")                                                            \
    for (int i_ = 0; i_ < 4; i_++) {                                             \
        int e_ = tid + i_ * 256;                                                 \
        int row_ = e_ >> 3, cc_ = e_ & 7;                                        \
        uint32_t sw_ = (uint32_t)((cc_ ^ (row_ & 7)) * 16);                      \
        CP_ASYNC16(dA + row_ * 128 + sw_,                                        \
                   baseA + (size_t)row_ * 512 + (chunk) * 128 + cc_ * 16);       \
        CP_ASYNC16(dB + row_ * 128 + sw_,                                        \
                   baseB + (size_t)row_ * 512 + (chunk) * 128 + cc_ * 16);       \
    }                                                                            \
    CP_COMMIT();                                                                 \
} while (0)

    ISSUE_CHUNK(0, 0);
    ISSUE_CHUNK(1, 1);

    const int r7   = lane & 7;
    const int rA   = wm * 64 + (lane & 15);
    const int khA  = lane >> 4;
    const int nB4  = wn * 32 + ((lane >> 4) & 1) * 8 + r7;
    const int khB4 = (lane >> 3) & 1;

    uint32_t tA[4], tB[4];
#pragma unroll
    for (int kt = 0; kt < 4; kt++) {
        tA[kt] = (uint32_t)((((kt * 2 + khA)  ^ r7)) * 16);
        tB[kt] = (uint32_t)((((kt * 2 + khB4) ^ r7)) * 16);
    }
    uint32_t baseA_mt[4], baseB_nt2[2];
#pragma unroll
    for (int mt = 0; mt < 4; mt++) baseA_mt[mt] = (uint32_t)((rA + mt * 16) * 128);
#pragma unroll
    for (int n2 = 0; n2 < 2; n2++) baseB_nt2[n2] = (uint32_t)((nB4 + n2 * 16) * 128);

    for (int ch = 0; ch < 4; ch++) {
        int st = ch % 3;
        if (ch == 3) { CP_WAIT0(); } else { CP_WAIT1(); }
        __syncthreads();
        if (ch + 2 < 4) ISSUE_CHUNK(ch + 2, (ch + 2) % 3);

        uint32_t Ab = smb + st * 32768u;
        uint32_t Bb = Ab + 16384u;
#pragma unroll
        for (int kt = 0; kt < 4; kt++) {
            uint32_t a[4][4], bfr[4][2];
#pragma unroll
            for (int mt = 0; mt < 4; mt++) {
                LDSM_X4(a[mt][0], a[mt][1], a[mt][2], a[mt][3],
                        Ab + baseA_mt[mt] + tA[kt]);
            }
#pragma unroll
            for (int n2 = 0; n2 < 2; n2++) {
                LDSM_X4(bfr[2 * n2][0], bfr[2 * n2][1],
                        bfr[2 * n2 + 1][0], bfr[2 * n2 + 1][1],
                        Bb + baseB_nt2[n2] + tB[kt]);
            }
#pragma unroll
            for (int mt = 0; mt < 4; mt++)
#pragma unroll
                for (int nt = 0; nt < 4; nt++) MMA16816(c[mt][nt], a[mt], bfr[nt]);
        }
    }
#undef ISSUE_CHUNK

    float cn16[4][2];
#pragma unroll
    for (int nt = 0; nt < 4; nt++) {
        int col0 = bx * 128 + wn * 32 + nt * 8 + (lane & 3) * 2;
        cn16[nt][0] = g_cnorm[col0]     + DBIAS;
        cn16[nt][1] = g_cnorm[col0 + 1] + DBIAS;
    }
#pragma unroll
    for (int mt = 0; mt < 4; mt++) {
#pragma unroll
        for (int h = 0; h < 2; h++) {
            unsigned long long b1 = ~0ull, b2 = ~0ull;
#pragma unroll
            for (int nt = 0; nt < 4; nt++) {
#pragma unroll
                for (int j = 0; j < 2; j++) {
                    int col = bx * 128 + wn * 32 + nt * 8 + (lane & 3) * 2 + j;
                    float d = fmaf(-2.f, c[mt][nt][h * 2 + j], cn16[nt][j]);
                    unsigned long long p =
                        ((unsigned long long)__float_as_uint(d) << 32) | (unsigned)col;
                    if (p < b1) { b2 = b1; b1 = p; }
                    else if (p < b2) { b2 = p; }
                }
            }
#pragma unroll
            for (int x = 1; x <= 2; x <<= 1) {
                unsigned long long o1 = __shfl_xor_sync(0xFFFFFFFFu, b1, x);
                unsigned long long o2 = __shfl_xor_sync(0xFFFFFFFFu, b2, x);
                unsigned long long w1 = u64min(b1, o1);
                unsigned long long l1 = u64max(b1, o1);
                b2 = u64min(l1, u64min(b2, o2));
                b1 = w1;
            }
            if ((lane & 3) == 0) {
                int token = by * 128 + wm * 64 + mt * 16 + (lane >> 2) + h * 8;
                int g = bx * 4 + wn;
                g_part[(size_t)token * 512 + g * 2 + 0] = b1;
                g_part[(size_t)token * 512 + g * 2 + 1] = b2;
            }
        }
    }
}

// ---------------- select: coarse min + margin + exact fp32 rerank ----------------
__global__ void __launch_bounds__(256)
select_k(const float* __restrict__ cbk, float* __restrict__ out_idx) {
    __shared__ int s_cnt[8];
    __shared__ unsigned s_code[8][64];
    int w = threadIdx.x >> 5, lane = threadIdx.x & 31;
    int token = blockIdx.x * 8 + w;
    if (lane == 0) s_cnt[w] = 0;
    __syncwarp();

    unsigned long long v[16];
    unsigned long long m = ~0ull;
#pragma unroll
    for (int i = 0; i < 16; i++) {
        v[i] = g_part[(size_t)token * 512 + i * 32 + lane];
        m = u64min(m, v[i]);
    }
#pragma unroll
    for (int x = 16; x; x >>= 1) {
        unsigned long long o = __shfl_xor_sync(0xFFFFFFFFu, m, x);
        m = u64min(m, o);
    }
    unsigned ub = (unsigned)(m >> 32);
    float dbest_b = __uint_as_float(ub);
    unsigned tb = __float_as_uint(dbest_b + MARGIN);
#pragma unroll
    for (int i = 0; i < 16; i++) {
        if ((unsigned)(v[i] >> 32) <= tb) {
            int p = atomicAdd(&s_cnt[w], 1);
            if (p < 64) s_code[w][p] = (unsigned)v[i];
        }
    }
    __syncwarp();
    int n = s_cnt[w] < 64 ? s_cnt[w] : 64;

    unsigned winner;
    if (n <= 1) {
        winner = (unsigned)m;
    } else {
        float e[8];
        *(float4*)e       = *(const float4*)(g_enc + (size_t)token * 256 + lane * 8);
        *(float4*)(e + 4) = *(const float4*)(g_enc + (size_t)token * 256 + lane * 8 + 4);
        unsigned long long best = ~0ull;
        for (int s = 0; s < n; s++) {
            unsigned code = s_code[w][s];
            const float* cr = cbk + (size_t)code * 256 + lane * 8;
            float part = 0.f;
#pragma unroll
            for (int j = 0; j < 8; j++) part += e[j] * cr[j];
#pragma unroll
            for (int x = 16; x; x >>= 1) part += __shfl_xor_sync(0xFFFFFFFFu, part, x);
            float d = g_cnorm[code] - 2.f * part + DBIAS;
            unsigned long long p = ((unsigned long long)__float_as_uint(d) << 32) | code;
            best = u64min(best, p);
        }
        winner = (unsigned)best;
    }
    if (lane == 0) {
        g_idx[token] = (int)winner;
        if (out_idx) out_idx[token] = (float)winner;
    }
}

// ---------------- gather (o-dim split across gridDim.z = 8) ----------------
__global__ void gather_out(const float* __restrict__ out_b, float* __restrict__ out) {
    int b  = blockIdx.y;
    int t0 = blockIdx.x * 64;
    int obase = blockIdx.z * (DDIM / 8);
    __shared__ float sm[64][65];
    __shared__ int sidx[64];
    int tid = threadIdx.x;
    if (tid < 64) sidx[tid] = g_idx[b * TDIM + t0 + tid];
    __syncthreads();

    for (int o0 = obase; o0 < obase + DDIM / 8; o0 += 64) {
#pragma unroll
        for (int p = 0; p < 16; p++) {
            int e  = tid + p * 256;
            int tl = e >> 6, ol = e & 63;
            sm[tl][ol] = g_table[(size_t)sidx[tl] * DDIM + o0 + ol];
        }
        __syncthreads();
#pragma unroll
        for (int p = 0; p < 16; p++) {
            int e  = tid + p * 256;
            int ol = e >> 6, tl = e & 63;
            out[(size_t)b * DDIM * TDIM + (size_t)(o0 + ol) * TDIM + t0 + tl] =
                sm[tl][ol] + out_b[o0 + ol];
        }
        __syncthreads();
    }
}

// ---------------- launch ----------------
extern "C" void kernel_launch(void* const* d_in, const int* in_sizes, int n_in,
                              void* d_out, int out_size) {
    const float* z     = (const float*)d_in[0];
    const float* in_v  = (const float*)d_in[1];
    const float* in_g  = (const float*)d_in[2];
    const float* in_b  = (const float*)d_in[3];
    const float* out_v = (const float*)d_in[4];
    const float* out_g = (const float*)d_in[5];
    const float* out_b = (const float*)d_in[6];
    const float* cbk   = (const float*)d_in[7];
    float* out = (float*)d_out;

    cudaFuncSetAttribute(gemm_ze_mma, cudaFuncAttributeMaxDynamicSharedMemorySize, 73728);
    cudaFuncSetAttribute(mega_coarse_table, cudaFuncAttributeMaxDynamicSharedMemorySize, 98304);

    const long long out_elems = (long long)BATCH * DDIM * TDIM;
    float* idx_dst = (out_size >= out_elems + M_TOK) ? out + out_elems : nullptr;

    prep_mega        <<<10496, 256>>>(cbk, in_v, in_g, out_v, out_g, z);   // 1
    gemm_ze_mma      <<<dim3(2, 512), 256, 73728>>>(in_b);                 // 2
    mega_coarse_table<<<16896, 256, 98304>>>(cbk);                         // 3
    select_k         <<<M_TOK / 8, 256>>>(cbk, idx_dst);                   // 4  <- profiled
    gather_out       <<<dim3(TDIM / 64, BATCH, 8), 256>>>(out_b, out);     // 5
}